// round 10
// baseline (speedup 1.0000x reference)
#include <cuda_runtime.h>
#include <cuda_fp16.h>
#include <cstdint>

#define DIN    128
#define DOUT   128
#define TILE   64
#define THREADS 256

// ---- smem layout (per CTA ~108.5KB -> 2 CTAs/SM) ----
// W frags: [s=0..7][pair=0..7][lane]*16B = 32KB
#define OFF_WH     0
// A frag stages: [f=0..31][g=0..7][c'=0..7] 8B units; g-pitch 80B, f-pitch 640B
#define OFF_FRAG(st) (32768 + (st)*20480)
// out staging: 64 rows x 132 f32
#define OFF_OUT    73728
#define OFF_BIAS   107520
#define OFF_B2     108032
#define OFF_XN2(st) (108048 + (st)*256)
#define OFF_RS2    108560
#define OFF_RSB    109584
#define OFF_CA     110608
#define OFF_CB     110864
#define SMEM_TOTAL 111120

// named barriers
#define BAR_FULL(s)  (1 + (s))
#define BAR_EMPTY(s) (3 + (s))
#define BAR_CONS     5
#define BAR_OFULL    6
#define BAR_OEMPTY   7

__device__ __forceinline__ void bar_sync256(int id) {
    asm volatile("bar.sync %0, %1;" :: "r"(id), "r"(256) : "memory");
}
__device__ __forceinline__ void bar_arrive256(int id) {
    asm volatile("bar.arrive %0, %1;" :: "r"(id), "r"(256) : "memory");
}
__device__ __forceinline__ void bar_sync128(int id) {
    asm volatile("bar.sync %0, %1;" :: "r"(id), "r"(128) : "memory");
}
__device__ __forceinline__ uint32_t packh(float hi, float lo) {
    uint32_t r; asm("cvt.rn.f16x2.f32 %0, %1, %2;" : "=r"(r) : "f"(hi), "f"(lo)); return r;
}
__device__ __forceinline__ void mma_f16(float4& d, uint32_t a0, uint32_t a1,
                                        uint32_t a2, uint32_t a3,
                                        uint32_t b0, uint32_t b1) {
    asm volatile("mma.sync.aligned.m16n8k16.row.col.f32.f16.f16.f32 "
        "{%0,%1,%2,%3}, {%4,%5,%6,%7}, {%8,%9}, {%0,%1,%2,%3};"
        : "+f"(d.x), "+f"(d.y), "+f"(d.z), "+f"(d.w)
        : "r"(a0), "r"(a1), "r"(a2), "r"(a3), "r"(b0), "r"(b1));
}

extern "C" __global__ void __launch_bounds__(THREADS, 2)
mobius_ws2_kernel(const float* __restrict__ X,
                  const float* __restrict__ W,
                  const float* __restrict__ bias,
                  float* __restrict__ out,
                  int nrows)
{
    extern __shared__ __align__(16) char smem[];
    float* sbias = (float*)(smem + OFF_BIAS);
    float* sB2   = (float*)(smem + OFF_B2);
    float* rs2   = (float*)(smem + OFF_RS2);
    float* rsb   = (float*)(smem + OFF_RSB);
    float* cA    = (float*)(smem + OFF_CA);
    float* cB    = (float*)(smem + OFF_CB);
    float* obuf  = (float*)(smem + OFF_OUT);

    const int tid  = threadIdx.x;
    const int lane = tid & 31;
    const int wid  = tid >> 5;
    const int g    = lane >> 2;
    const int cg   = lane & 3;

    if (tid < 128) sbias[tid] = bias[tid];

    // ---- W conversion (once): warp wid = k-step s; fp16 ----
    {
        const float* wp0 = W + wid * 16 + 2 * cg;
        #pragma unroll
        for (int nt = 0; nt < 16; nt++) {
            int n = nt * 8 + g;
            const float* wp = wp0 + n * DIN;
            float2 u0 = *(const float2*)(wp);
            float2 u1 = *(const float2*)(wp + 8);
            uint2 vh;
            vh.x = packh(u0.y, u0.x);
            vh.y = packh(u1.y, u1.x);
            int p = nt >> 1, half = nt & 1;
            *(uint2*)(smem + OFF_WH + ((wid * 8 + p) * 32 + lane) * 16 + half * 8) = vh;
        }
    }
    __syncthreads();
    if (tid < 32) {
        float s = 0.f;
        #pragma unroll
        for (int i = 0; i < 4; i++) { float v = sbias[tid + 32 * i]; s = fmaf(v, v, s); }
        #pragma unroll
        for (int o = 16; o; o >>= 1) s += __shfl_xor_sync(0xffffffffu, s, o);
        if (tid == 0) *sB2 = s;
    }
    __syncthreads();   // last CTA-wide barrier

    const int ntiles = nrows / TILE;
    const int gstep  = gridDim.x;

    if (wid < 4) {
        // ========== PRODUCER: convert X -> frag units; drain out buffer ====
        const int p = wid;   // frag-row p: rows p*16+g, p*16+8+g
        long long prev_rowbase = 0;
        int i = 0;
        for (int t = blockIdx.x; t < ntiles; t += gstep, i++) {
            const int st = i & 1;
            if (i >= 2) bar_sync256(BAR_EMPTY(st));

            const long long rowbase = (long long)t * TILE;
            const float* p0 = X + (rowbase + p * 16 + g) * DIN + 4 * cg;
            const float* p1 = p0 + 8 * DIN;
            char* fb = smem + OFF_FRAG(st) + (p * 8) * 640 + g * 80 + cg * 16;
            float xa0 = 0.f, xa1 = 0.f;
            #pragma unroll
            for (int s = 0; s < 8; s++) {
                float4 a0 = *(const float4*)(p0 + 16 * s);
                float4 a1 = *(const float4*)(p1 + 16 * s);
                xa0 = fmaf(a0.x, a0.x, xa0); xa0 = fmaf(a0.y, a0.y, xa0);
                xa0 = fmaf(a0.z, a0.z, xa0); xa0 = fmaf(a0.w, a0.w, xa0);
                xa1 = fmaf(a1.x, a1.x, xa1); xa1 = fmaf(a1.y, a1.y, xa1);
                xa1 = fmaf(a1.z, a1.z, xa1); xa1 = fmaf(a1.w, a1.w, xa1);
                uint2 u0, u1;
                u0.x = packh(a0.y, a0.x);  u0.y = packh(a1.y, a1.x);   // c' = 2cg
                u1.x = packh(a0.w, a0.z);  u1.y = packh(a1.w, a1.z);   // c' = 2cg+1
                *(uint2*)(fb + s * 640)     = u0;
                *(uint2*)(fb + s * 640 + 8) = u1;
            }
            xa0 += __shfl_xor_sync(0xffffffffu, xa0, 1);
            xa0 += __shfl_xor_sync(0xffffffffu, xa0, 2);
            xa1 += __shfl_xor_sync(0xffffffffu, xa1, 1);
            xa1 += __shfl_xor_sync(0xffffffffu, xa1, 2);
            if (cg == 0) {
                float* xn = (float*)(smem + OFF_XN2(st));
                xn[p * 16 + g]     = xa0;
                xn[p * 16 + g + 8] = xa1;
            }
            __threadfence_block();
            bar_arrive256(BAR_FULL(st));

            // ---- drain out staging of previous tile (coalesced) ----
            if (i >= 1) {
                bar_sync256(BAR_OFULL);
                float* dst = out + (prev_rowbase + p * 16) * DOUT + lane * 4;
                const float* src = obuf + (p * 16) * 132 + lane * 4;
                #pragma unroll
                for (int rr = 0; rr < 16; rr++) {
                    float4 v = *(const float4*)(src + rr * 132);
                    *(float4*)(dst + rr * DOUT) = v;
                }
                bar_arrive256(BAR_OEMPTY);
            }
            prev_rowbase = rowbase;
        }
        // final drain
        if (i >= 1) {
            bar_sync256(BAR_OFULL);
            float* dst = out + (prev_rowbase + p * 16) * DOUT + lane * 4;
            const float* src = obuf + (p * 16) * 132 + lane * 4;
            #pragma unroll
            for (int rr = 0; rr < 16; rr++) {
                float4 v = *(const float4*)(src + rr * 132);
                *(float4*)(dst + rr * DOUT) = v;
            }
        }
    } else {
        // ========== CONSUMER: MMA (m64 x n32) + epilogue + STS out ==========
        const int c    = wid - 4;      // n-quarter: cols c*32 .. c*32+31
        const int ctid = tid - 128;
        const float b2c = *sB2;

        float2 bj[4];
        #pragma unroll
        for (int j = 0; j < 4; j++)
            bj[j] = *(const float2*)(sbias + c * 32 + j * 8 + 2 * cg);

        int i = 0;
        for (int t = blockIdx.x; t < ntiles; t += gstep, i++) {
            const int st = i & 1;

            bar_sync256(BAR_FULL(st));

            // ---- mainloop: 1-pass fp16, warp tile m64 x n32 ----
            float4 acc[4][4];
            #pragma unroll
            for (int ii = 0; ii < 4; ii++)
                #pragma unroll
                for (int j = 0; j < 4; j++) acc[ii][j] = make_float4(0.f, 0.f, 0.f, 0.f);

            #pragma unroll
            for (int s = 0; s < 8; s++) {
                uint2 alo[4], ahi[4];
                uint4 wh[2];
                #pragma unroll
                for (int ii = 0; ii < 4; ii++) {
                    const char* fb = smem + OFF_FRAG(st) + (ii * 8 + s) * 640 + g * 80;
                    alo[ii] = *(const uint2*)(fb + cg * 8);
                    ahi[ii] = *(const uint2*)(fb + (cg + 4) * 8);
                }
                #pragma unroll
                for (int u = 0; u < 2; u++)
                    wh[u] = *(const uint4*)(smem + OFF_WH
                              + ((s * 8 + c * 2 + u) * 32 + lane) * 16);
                #pragma unroll
                for (int ii = 0; ii < 4; ii++)
                    #pragma unroll
                    for (int u = 0; u < 2; u++) {
                        mma_f16(acc[ii][2*u],   alo[ii].x, alo[ii].y, ahi[ii].x, ahi[ii].y,
                                wh[u].x, wh[u].y);
                        mma_f16(acc[ii][2*u+1], alo[ii].x, alo[ii].y, ahi[ii].x, ahi[ii].y,
                                wh[u].z, wh[u].w);
                    }
            }

            // ---- reductions per row: ||Mx||^2, <Mx,bias> ----
            #pragma unroll
            for (int ii = 0; ii < 4; ii++) {
                float s2r0 = 0.f, s2r1 = 0.f, sbr0 = 0.f, sbr1 = 0.f;
                #pragma unroll
                for (int j = 0; j < 4; j++) {
                    float4 d = acc[ii][j];
                    s2r0 = fmaf(d.x, d.x, s2r0); s2r0 = fmaf(d.y, d.y, s2r0);
                    s2r1 = fmaf(d.z, d.z, s2r1); s2r1 = fmaf(d.w, d.w, s2r1);
                    sbr0 = fmaf(d.x, bj[j].x, sbr0); sbr0 = fmaf(d.y, bj[j].y, sbr0);
                    sbr1 = fmaf(d.z, bj[j].x, sbr1); sbr1 = fmaf(d.w, bj[j].y, sbr1);
                }
                s2r0 += __shfl_xor_sync(0xffffffffu, s2r0, 1);
                s2r0 += __shfl_xor_sync(0xffffffffu, s2r0, 2);
                s2r1 += __shfl_xor_sync(0xffffffffu, s2r1, 1);
                s2r1 += __shfl_xor_sync(0xffffffffu, s2r1, 2);
                sbr0 += __shfl_xor_sync(0xffffffffu, sbr0, 1);
                sbr0 += __shfl_xor_sync(0xffffffffu, sbr0, 2);
                sbr1 += __shfl_xor_sync(0xffffffffu, sbr1, 1);
                sbr1 += __shfl_xor_sync(0xffffffffu, sbr1, 2);
                if (cg == 0) {
                    int r0 = ii * 16 + g;
                    rs2[r0 * 4 + c]       = s2r0;
                    rs2[(r0 + 8) * 4 + c] = s2r1;
                    rsb[r0 * 4 + c]       = sbr0;
                    rsb[(r0 + 8) * 4 + c] = sbr1;
                }
            }
            bar_sync128(BAR_CONS);

            // ---- per-row coefficients ----
            if (ctid < TILE) {
                int r = ctid;
                const float* xn2st = (const float*)(smem + OFF_XN2(st));
                float4 a4 = *(const float4*)(rs2 + r * 4);
                float4 b4 = *(const float4*)(rsb + r * 4);
                float mxn2 = (a4.x + a4.y) + (a4.z + a4.w);
                float dotb = (b4.x + b4.y) + (b4.z + b4.w);
                float xn  = fmaxf(sqrtf(xn2st[r]), 1e-15f);
                float mxn = fmaxf(sqrtf(mxn2),     1e-15f);
                float u   = fminf(xn, 1.0f - 1e-7f);
                float at  = 0.5f * (log1pf(u) - log1pf(-u));
                float sc  = tanhf(mxn / xn * at) / mxn;
                if (mxn <= 1e-10f) sc = 0.0f;
                float xy    = sc * dotb;
                float y2    = sc * sc * mxn2;
                float alpha = 1.0f + 2.0f * xy + b2c;
                float beta  = 1.0f - y2;
                float den   = fmaxf(1.0f + 2.0f * xy + y2 * b2c, 1e-15f);
                float A  = sc * alpha / den;
                float Bc = beta / den;
                float o2 = A * A * mxn2 + 2.0f * A * Bc * dotb + Bc * Bc * b2c;
                float on = fmaxf(sqrtf(o2), 1e-15f);
                float mxv = 1.0f - 1e-5f;
                float fpr = (on > mxv) ? (mxv / on) : 1.0f;
                cA[r] = A * fpr;
                cB[r] = Bc * fpr;
            }
            bar_sync128(BAR_CONS);

            // frag stage fully consumed (A in mainloop, xn2 in coef)
            if (t + 2 * gstep < ntiles)
                bar_arrive256(BAR_EMPTY(st));

            // ---- finals -> out staging buffer (STS.64, 2-way max) ----
            if (i >= 1) bar_sync256(BAR_OEMPTY);
            #pragma unroll
            for (int ii = 0; ii < 4; ii++) {
                int r0 = ii * 16 + g;
                float A0 = cA[r0],     B0 = cB[r0];
                float A1 = cA[r0 + 8], B1 = cB[r0 + 8];
                float* op0 = obuf + r0 * 132 + c * 32 + 2 * cg;
                float* op1 = op0 + 8 * 132;
                #pragma unroll
                for (int j = 0; j < 4; j++) {
                    float4 d = acc[ii][j];
                    float2 o0, o1;
                    o0.x = fmaf(A0, d.x, B0 * bj[j].x);
                    o0.y = fmaf(A0, d.y, B0 * bj[j].y);
                    o1.x = fmaf(A1, d.z, B1 * bj[j].x);
                    o1.y = fmaf(A1, d.w, B1 * bj[j].y);
                    *(float2*)(op0 + j * 8) = o0;
                    *(float2*)(op1 + j * 8) = o1;
                }
            }
            __threadfence_block();
            bar_arrive256(BAR_OFULL);
        }
    }
}

extern "C" void kernel_launch(void* const* d_in, const int* in_sizes, int n_in,
                              void* d_out, int out_size) {
    const float* X    = (const float*)d_in[0];
    const float* W    = (const float*)d_in[1];
    const float* bias = (const float*)d_in[2];
    float* out = (float*)d_out;

    int nrows = in_sizes[0] / DIN;

    cudaFuncSetAttribute(mobius_ws2_kernel,
                         cudaFuncAttributeMaxDynamicSharedMemorySize, SMEM_TOTAL);

    int nsm = 148;
    cudaDeviceGetAttribute(&nsm, cudaDevAttrMultiProcessorCount, 0);
    int ntiles = nrows / TILE;
    int grid = 2 * nsm;
    if (grid > ntiles) grid = ntiles;

    mobius_ws2_kernel<<<grid, THREADS, SMEM_TOTAL>>>(X, W, bias, out, nrows);
}

// round 11
// speedup vs baseline: 1.0837x; 1.0837x over previous
#include <cuda_runtime.h>
#include <cuda_fp16.h>
#include <cstdint>

#define DIN    128
#define DOUT   128
#define TILE   64
#define THREADS 256
#define NST    4

// ---- smem layout (per CTA ~100KB -> 2 CTAs/SM) ----
#define OFF_WH     0                          // 8s x 8pairs x 32 x 16B = 32KB
#define AH_ST(s)   (32768 + (s)*16384)        // 16KB per stage (fp16 hi)
#define OFF_BIAS   98304                      // 128 f32
#define OFF_B2     98816
#define OFF_XN2(s) (98832 + (s)*256)          // [64] f32 per stage
#define OFF_RS2    99856                      // [64][4] f32
#define OFF_RSB    100880
#define OFF_CA     101904
#define OFF_CB     102160
#define SMEM_TOTAL 102416

// named barriers: 1..4 = full(stage), 5..8 = empty(stage), 9 = consumer-internal
#define BAR_FULL(s)  (1 + (s))
#define BAR_EMPTY(s) (5 + (s))
#define BAR_CONS     9

__device__ __forceinline__ void bar_sync256(int id) {
    asm volatile("bar.sync %0, %1;" :: "r"(id), "r"(256) : "memory");
}
__device__ __forceinline__ void bar_arrive256(int id) {
    asm volatile("bar.arrive %0, %1;" :: "r"(id), "r"(256) : "memory");
}
__device__ __forceinline__ void bar_sync128(int id) {
    asm volatile("bar.sync %0, %1;" :: "r"(id), "r"(128) : "memory");
}

__device__ __forceinline__ uint32_t packh(float hi, float lo) {
    uint32_t r; asm("cvt.rn.f16x2.f32 %0, %1, %2;" : "=r"(r) : "f"(hi), "f"(lo)); return r;
}
__device__ __forceinline__ void mma_f16(float4& d, const uint4& a, uint32_t b0, uint32_t b1) {
    asm volatile("mma.sync.aligned.m16n8k16.row.col.f32.f16.f16.f32 "
        "{%0,%1,%2,%3}, {%4,%5,%6,%7}, {%8,%9}, {%0,%1,%2,%3};"
        : "+f"(d.x), "+f"(d.y), "+f"(d.z), "+f"(d.w)
        : "r"(a.x), "r"(a.y), "r"(a.z), "r"(a.w), "r"(b0), "r"(b1));
}

extern "C" __global__ void __launch_bounds__(THREADS, 2)
mobius_ws4s_kernel(const float* __restrict__ X,
                   const float* __restrict__ W,
                   const float* __restrict__ bias,
                   float* __restrict__ out,
                   int nrows)
{
    extern __shared__ __align__(16) char smem[];
    float* sbias = (float*)(smem + OFF_BIAS);
    float* sB2   = (float*)(smem + OFF_B2);
    float* rs2   = (float*)(smem + OFF_RS2);
    float* rsb   = (float*)(smem + OFF_RSB);
    float* cA    = (float*)(smem + OFF_CA);
    float* cB    = (float*)(smem + OFF_CB);

    const int tid  = threadIdx.x;
    const int lane = tid & 31;
    const int wid  = tid >> 5;
    const int g    = lane >> 2;
    const int cg   = lane & 3;

    if (tid < 128) sbias[tid] = bias[tid];

    // ---- W conversion (once, all 8 warps): warp wid = k-step s; fp16 ----
    {
        const float* wp0 = W + wid * 16 + 2 * cg;
        #pragma unroll
        for (int nt = 0; nt < 16; nt++) {
            int n = nt * 8 + g;
            const float* wp = wp0 + n * DIN;
            float2 u0 = *(const float2*)(wp);
            float2 u1 = *(const float2*)(wp + 8);
            uint2 vh;
            vh.x = packh(u0.y, u0.x);
            vh.y = packh(u1.y, u1.x);
            int p = nt >> 1, half = nt & 1;
            *(uint2*)(smem + OFF_WH + ((wid * 8 + p) * 32 + lane) * 16 + half * 8) = vh;
        }
    }
    __syncthreads();
    if (tid < 32) {
        float s = 0.f;
        #pragma unroll
        for (int i = 0; i < 4; i++) { float v = sbias[tid + 32 * i]; s = fmaf(v, v, s); }
        #pragma unroll
        for (int o = 16; o; o >>= 1) s += __shfl_xor_sync(0xffffffffu, s, o);
        if (tid == 0) *sB2 = s;
    }
    __syncthreads();   // last CTA-wide barrier

    const int ntiles = nrows / TILE;
    const int gstep  = gridDim.x;

    if (wid < 4) {
        // ========== PRODUCER: X -> fp16 frags (hi only) + xn2 ==========
        const int p = wid;   // frag-row p: rows p*16+g, p*16+8+g
        int i = 0;
        for (int t = blockIdx.x; t < ntiles; t += gstep, i++) {
            const int st = i & (NST - 1);
            if (i >= NST) bar_sync256(BAR_EMPTY(st));

            const long long rowbase = (long long)t * TILE;
            const float* p0 = X + (rowbase + p * 16 + g) * DIN + 2 * cg;
            const float* p1 = p0 + 8 * DIN;
            float xa0 = 0.f, xa1 = 0.f;
            #pragma unroll
            for (int s = 0; s < 8; s++) {
                float2 v00 = *(const float2*)(p0 + 16 * s);
                float2 v01 = *(const float2*)(p0 + 16 * s + 8);
                float2 v10 = *(const float2*)(p1 + 16 * s);
                float2 v11 = *(const float2*)(p1 + 16 * s + 8);
                xa0 = fmaf(v00.x, v00.x, xa0); xa0 = fmaf(v00.y, v00.y, xa0);
                xa0 = fmaf(v01.x, v01.x, xa0); xa0 = fmaf(v01.y, v01.y, xa0);
                xa1 = fmaf(v10.x, v10.x, xa1); xa1 = fmaf(v10.y, v10.y, xa1);
                xa1 = fmaf(v11.x, v11.x, xa1); xa1 = fmaf(v11.y, v11.y, xa1);
                uint4 h;
                h.x = packh(v00.y, v00.x);
                h.y = packh(v10.y, v10.x);
                h.z = packh(v01.y, v01.x);
                h.w = packh(v11.y, v11.x);
                *(uint4*)(smem + AH_ST(st) + ((p * 8 + s) * 32 + lane) * 16) = h;
            }
            xa0 += __shfl_xor_sync(0xffffffffu, xa0, 1);
            xa0 += __shfl_xor_sync(0xffffffffu, xa0, 2);
            xa1 += __shfl_xor_sync(0xffffffffu, xa1, 1);
            xa1 += __shfl_xor_sync(0xffffffffu, xa1, 2);
            if (cg == 0) {
                float* xn = (float*)(smem + OFF_XN2(st));
                xn[p * 16 + g]     = xa0;
                xn[p * 16 + g + 8] = xa1;
            }
            __threadfence_block();
            bar_arrive256(BAR_FULL(st));
        }
    } else {
        // ========== CONSUMER: MMA (m64 x n32) + epilogue + stores ==========
        const int c    = wid - 4;      // n-quarter: cols c*32 .. c*32+31
        const int ctid = tid - 128;
        const float b2c = *sB2;

        int i = 0;
        for (int t = blockIdx.x; t < ntiles; t += gstep, i++) {
            const int st = i & (NST - 1);
            const long long rowbase = (long long)t * TILE;

            bar_sync256(BAR_FULL(st));

            // ---- mainloop: 1-pass fp16, warp tile m64 x n32 ----
            float4 acc[4][4];
            #pragma unroll
            for (int ii = 0; ii < 4; ii++)
                #pragma unroll
                for (int j = 0; j < 4; j++) acc[ii][j] = make_float4(0.f, 0.f, 0.f, 0.f);

            #pragma unroll
            for (int s = 0; s < 8; s++) {
                uint4 ah[4], wh[2];
                #pragma unroll
                for (int ii = 0; ii < 4; ii++)
                    ah[ii] = *(const uint4*)(smem + AH_ST(st)
                              + ((ii * 8 + s) * 32 + lane) * 16);
                #pragma unroll
                for (int u = 0; u < 2; u++)
                    wh[u] = *(const uint4*)(smem + OFF_WH
                              + ((s * 8 + c * 2 + u) * 32 + lane) * 16);
                #pragma unroll
                for (int ii = 0; ii < 4; ii++)
                    #pragma unroll
                    for (int u = 0; u < 2; u++) {
                        mma_f16(acc[ii][2*u],   ah[ii], wh[u].x, wh[u].y);
                        mma_f16(acc[ii][2*u+1], ah[ii], wh[u].z, wh[u].w);
                    }
            }

            // ---- reductions per row: ||Mx||^2, <Mx,bias> ----
            float2 bj[4];
            #pragma unroll
            for (int j = 0; j < 4; j++)
                bj[j] = *(const float2*)(sbias + c * 32 + j * 8 + 2 * cg);

            #pragma unroll
            for (int ii = 0; ii < 4; ii++) {
                float s2r0 = 0.f, s2r1 = 0.f, sbr0 = 0.f, sbr1 = 0.f;
                #pragma unroll
                for (int j = 0; j < 4; j++) {
                    float4 d = acc[ii][j];
                    s2r0 = fmaf(d.x, d.x, s2r0); s2r0 = fmaf(d.y, d.y, s2r0);
                    s2r1 = fmaf(d.z, d.z, s2r1); s2r1 = fmaf(d.w, d.w, s2r1);
                    sbr0 = fmaf(d.x, bj[j].x, sbr0); sbr0 = fmaf(d.y, bj[j].y, sbr0);
                    sbr1 = fmaf(d.z, bj[j].x, sbr1); sbr1 = fmaf(d.w, bj[j].y, sbr1);
                }
                s2r0 += __shfl_xor_sync(0xffffffffu, s2r0, 1);
                s2r0 += __shfl_xor_sync(0xffffffffu, s2r0, 2);
                s2r1 += __shfl_xor_sync(0xffffffffu, s2r1, 1);
                s2r1 += __shfl_xor_sync(0xffffffffu, s2r1, 2);
                sbr0 += __shfl_xor_sync(0xffffffffu, sbr0, 1);
                sbr0 += __shfl_xor_sync(0xffffffffu, sbr0, 2);
                sbr1 += __shfl_xor_sync(0xffffffffu, sbr1, 1);
                sbr1 += __shfl_xor_sync(0xffffffffu, sbr1, 2);
                if (cg == 0) {
                    int r0 = ii * 16 + g;
                    rs2[r0 * 4 + c]       = s2r0;
                    rs2[(r0 + 8) * 4 + c] = s2r1;
                    rsb[r0 * 4 + c]       = sbr0;
                    rsb[(r0 + 8) * 4 + c] = sbr1;
                }
            }
            bar_sync128(BAR_CONS);

            // ---- per-row coefficients ----
            if (ctid < TILE) {
                int r = ctid;
                const float* xn2st = (const float*)(smem + OFF_XN2(st));
                float4 a4 = *(const float4*)(rs2 + r * 4);
                float4 b4 = *(const float4*)(rsb + r * 4);
                float mxn2 = (a4.x + a4.y) + (a4.z + a4.w);
                float dotb = (b4.x + b4.y) + (b4.z + b4.w);
                float xn  = fmaxf(sqrtf(xn2st[r]), 1e-15f);
                float mxn = fmaxf(sqrtf(mxn2),     1e-15f);
                float u   = fminf(xn, 1.0f - 1e-7f);
                float at  = 0.5f * (log1pf(u) - log1pf(-u));
                float sc  = tanhf(mxn / xn * at) / mxn;
                if (mxn <= 1e-10f) sc = 0.0f;
                float xy    = sc * dotb;
                float y2    = sc * sc * mxn2;
                float alpha = 1.0f + 2.0f * xy + b2c;
                float beta  = 1.0f - y2;
                float den   = fmaxf(1.0f + 2.0f * xy + y2 * b2c, 1e-15f);
                float A  = sc * alpha / den;
                float Bc = beta / den;
                float o2 = A * A * mxn2 + 2.0f * A * Bc * dotb + Bc * Bc * b2c;
                float on = fmaxf(sqrtf(o2), 1e-15f);
                float mxv = 1.0f - 1e-5f;
                float fpr = (on > mxv) ? (mxv / on) : 1.0f;
                cA[r] = A * fpr;
                cB[r] = Bc * fpr;
            }
            bar_sync128(BAR_CONS);

            // stage fully consumed (frags in mainloop, xn2 in coef)
            if (t + NST * gstep < ntiles)
                bar_arrive256(BAR_EMPTY(st));

            // ---- stores: out = A[r]*Mx + B[r]*bias from regs ----
            #pragma unroll
            for (int ii = 0; ii < 4; ii++) {
                int r0 = ii * 16 + g;
                float A0 = cA[r0],     B0 = cB[r0];
                float A1 = cA[r0 + 8], B1 = cB[r0 + 8];
                float* op0 = out + (rowbase + r0) * DOUT + c * 32 + 2 * cg;
                float* op1 = op0 + 8 * DOUT;
                #pragma unroll
                for (int j = 0; j < 4; j++) {
                    float4 d = acc[ii][j];
                    float2 o0, o1;
                    o0.x = fmaf(A0, d.x, B0 * bj[j].x);
                    o0.y = fmaf(A0, d.y, B0 * bj[j].y);
                    o1.x = fmaf(A1, d.z, B1 * bj[j].x);
                    o1.y = fmaf(A1, d.w, B1 * bj[j].y);
                    *(float2*)(op0 + j * 8) = o0;
                    *(float2*)(op1 + j * 8) = o1;
                }
            }
            // cA/cB reuse safe: next write is after next BAR_CONS sync,
            // reached by this warp only after these stores issue.
        }
    }
}

extern "C" void kernel_launch(void* const* d_in, const int* in_sizes, int n_in,
                              void* d_out, int out_size) {
    const float* X    = (const float*)d_in[0];
    const float* W    = (const float*)d_in[1];
    const float* bias = (const float*)d_in[2];
    float* out = (float*)d_out;

    int nrows = in_sizes[0] / DIN;

    cudaFuncSetAttribute(mobius_ws4s_kernel,
                         cudaFuncAttributeMaxDynamicSharedMemorySize, SMEM_TOTAL);

    int nsm = 148;
    cudaDeviceGetAttribute(&nsm, cudaDevAttrMultiProcessorCount, 0);
    int ntiles = nrows / TILE;
    int grid = 2 * nsm;
    if (grid > ntiles) grid = ntiles;

    mobius_ws4s_kernel<<<grid, THREADS, SMEM_TOTAL>>>(X, W, bias, out, nrows);
}